// round 16
// baseline (speedup 1.0000x reference)
#include <cuda_runtime.h>
#include <cuda_bf16.h>
#include <cstdint>

#define FULLMASK 0xFFFFFFFFu

static constexpr int Bb = 2;
static constexpr int L  = 2048;
static constexpr int DM = 512;
static constexpr int H  = 8;
static constexpr int DK = 64;
static constexpr int U  = 38;     // int(5 * ln(2048)) = 38
static constexpr int BH = Bb * H; // 16
static constexpr int NC = 96;     // candidate buffer size (3 per lane)

// ---------------- scratch (static device globals; no allocation) ----------------
__device__ float g_Q[(size_t)BH * L * DK];     // 8 MB  head-major [bh][l][d]
__device__ float g_K[(size_t)BH * L * DK];     // 8 MB
__device__ float g_V[(size_t)BH * L * DK];     // 8 MB
__device__ __nv_bfloat16 g_Sb[(size_t)BH * L * L];  // 128 MB approx scores (bf16)
__device__ float g_AO[(size_t)Bb * L * DM];    // 8 MB
__device__ __nv_bfloat16 g_Qb[(size_t)BH * L * DK]; // 4 MB bf16 Q
__device__ __nv_bfloat16 g_Kb[(size_t)BH * L * DK]; // 4 MB bf16 K

// ---------------- packed fp32x2 helpers (sm_103a FFMA2) ----------------
__device__ __forceinline__ unsigned long long pk2(float lo, float hi)
{
    unsigned long long r;
    asm("mov.b64 %0, {%1, %2};" : "=l"(r) : "f"(lo), "f"(hi));
    return r;
}
__device__ __forceinline__ void upk2(unsigned long long p, float& lo, float& hi)
{
    asm("mov.b64 {%0, %1}, %2;" : "=f"(lo), "=f"(hi) : "l"(p));
}
__device__ __forceinline__ void ffma2(unsigned long long& d,
                                      unsigned long long a, unsigned long long b)
{
    asm("fma.rn.f32x2 %0, %1, %2, %0;" : "+l"(d) : "l"(a), "l"(b));
}

// =====================================================================
// FFMA2 SGEMM core, 64x128 tile: C(64x128) += A(64xK)*B(128xK)^T.
// 256 threads, microtile 4x8 (cols split 4+4, 64 apart), BK=16.
// Smaller tile -> ~80 regs -> 2-3 CTAs/SM for latency hiding.
// =====================================================================
__device__ __forceinline__ void gemm_core_64x128(
    const float* __restrict__ A, const float* __restrict__ Bm,
    int lda, int ldb, int Kc, float (&acc)[4][8])
{
    __shared__ float As[16][68];
    __shared__ float Bs[16][132];

    const int tid  = threadIdx.x;
    const int tx   = tid & 15;
    const int ty   = tid >> 4;
    const int arow = tid >> 2;         // 0..63
    const int lc   = (tid & 3) << 2;   // 0,4,8,12

    unsigned long long acc2[4][4];
    #pragma unroll
    for (int i = 0; i < 4; ++i)
        #pragma unroll
        for (int j = 0; j < 4; ++j) acc2[i][j] = 0ULL;

    float4 a0, b0, b1;
    a0 = *(const float4*)(A + (size_t)arow * lda + lc);
    b0 = *(const float4*)(Bm + (size_t)arow * ldb + lc);
    b1 = *(const float4*)(Bm + (size_t)(arow + 64) * ldb + lc);

    const int nk = Kc >> 4;
    for (int kt = 0; kt < nk; ++kt) {
        As[lc + 0][arow] = a0.x; As[lc + 1][arow] = a0.y;
        As[lc + 2][arow] = a0.z; As[lc + 3][arow] = a0.w;
        Bs[lc + 0][arow]      = b0.x; Bs[lc + 1][arow]      = b0.y;
        Bs[lc + 2][arow]      = b0.z; Bs[lc + 3][arow]      = b0.w;
        Bs[lc + 0][arow + 64] = b1.x; Bs[lc + 1][arow + 64] = b1.y;
        Bs[lc + 2][arow + 64] = b1.z; Bs[lc + 3][arow + 64] = b1.w;
        __syncthreads();

        if (kt + 1 < nk) {
            const int k0 = (kt + 1) << 4;
            a0 = *(const float4*)(A + (size_t)arow * lda + k0 + lc);
            b0 = *(const float4*)(Bm + (size_t)arow * ldb + k0 + lc);
            b1 = *(const float4*)(Bm + (size_t)(arow + 64) * ldb + k0 + lc);
        }

        #pragma unroll
        for (int c = 0; c < 16; ++c) {
            float4 af  = *(const float4*)&As[c][ty * 4];
            float4 bf0 = *(const float4*)&Bs[c][tx * 4];
            float4 bf1 = *(const float4*)&Bs[c][64 + tx * 4];

            unsigned long long ap[4], bp[4];
            ap[0] = pk2(af.x, af.x); ap[1] = pk2(af.y, af.y);
            ap[2] = pk2(af.z, af.z); ap[3] = pk2(af.w, af.w);
            bp[0] = pk2(bf0.x, bf0.y); bp[1] = pk2(bf0.z, bf0.w);
            bp[2] = pk2(bf1.x, bf1.y); bp[3] = pk2(bf1.z, bf1.w);

            #pragma unroll
            for (int i = 0; i < 4; ++i)
                #pragma unroll
                for (int j = 0; j < 4; ++j)
                    ffma2(acc2[i][j], ap[i], bp[j]);
        }
        __syncthreads();
    }

    #pragma unroll
    for (int i = 0; i < 4; ++i)
        #pragma unroll
        for (int j = 0; j < 4; ++j)
            upk2(acc2[i][j], acc[i][2 * j], acc[i][2 * j + 1]);
}

// =====================================================================
// Kernel 1: fused QKV projections (+ bf16 copy of Q,K for the MMA filter)
// grid (DM/128, B*L/64, 3)
// =====================================================================
__global__ __launch_bounds__(256)
void proj_kernel(const float* __restrict__ x,
                 const float* __restrict__ Wq, const float* __restrict__ bq,
                 const float* __restrict__ Wk, const float* __restrict__ bk,
                 const float* __restrict__ Wv, const float* __restrict__ bv)
{
    const float* W; const float* bias; float* dst;
    __nv_bfloat16* db = nullptr;
    if (blockIdx.z == 0)      { W = Wq; bias = bq; dst = g_Q; db = g_Qb; }
    else if (blockIdx.z == 1) { W = Wk; bias = bk; dst = g_K; db = g_Kb; }
    else                      { W = Wv; bias = bv; dst = g_V; }

    const float* A  = x + (size_t)blockIdx.y * 64 * DM;
    const float* Bm = W + (size_t)blockIdx.x * 128 * DM;

    float acc[4][8];
    gemm_core_64x128(A, Bm, DM, DM, DM, acc);

    const int tx = threadIdx.x & 15, ty = threadIdx.x >> 4;
    #pragma unroll
    for (int i = 0; i < 4; ++i) {
        const int gi = blockIdx.y * 64 + ty * 4 + i;
        const int b  = gi >> 11, l = gi & 2047;
        #pragma unroll
        for (int jh = 0; jh < 2; ++jh) {
            const int o = blockIdx.x * 128 + (jh ? 64 + tx * 4 : tx * 4);
            const int h = o >> 6, d = o & 63;
            float4 r = make_float4(acc[i][jh * 4 + 0] + bias[o + 0],
                                   acc[i][jh * 4 + 1] + bias[o + 1],
                                   acc[i][jh * 4 + 2] + bias[o + 2],
                                   acc[i][jh * 4 + 3] + bias[o + 3]);
            const size_t off = (((size_t)(b * H + h) * L) + l) * DK + d;
            *(float4*)&dst[off] = r;
            if (db) {
                __nv_bfloat16 hv[4] = {
                    __float2bfloat16(r.x), __float2bfloat16(r.y),
                    __float2bfloat16(r.z), __float2bfloat16(r.w)};
                *(uint64_t*)&db[off] = *(const uint64_t*)hv;
            }
        }
    }
}

// =====================================================================
// Kernel 2: S_approx = Qb Kb^T / 8 via warp-level bf16 mma.sync,
// stored bf16 with a smem-staged, fully coalesced epilogue.
// grid (L/128, L/128, BH), 256 threads = 8 warps (4Mx2N).
// =====================================================================
static constexpr int SMMA_STRIDE = 72;   // 144B rows -> LDSM conflict-free
static constexpr int STG_STRIDE  = 136;  // staging: 272B rows, 16B aligned

__device__ __forceinline__ void ldsm_x4(uint32_t& r0, uint32_t& r1,
                                        uint32_t& r2, uint32_t& r3, uint32_t a)
{
    asm volatile("ldmatrix.sync.aligned.m8n8.x4.shared.b16 {%0,%1,%2,%3}, [%4];"
                 : "=r"(r0), "=r"(r1), "=r"(r2), "=r"(r3) : "r"(a));
}
__device__ __forceinline__ void mma_bf16(float* d, const uint32_t* a, const uint32_t* b)
{
    asm volatile(
        "mma.sync.aligned.m16n8k16.row.col.f32.bf16.bf16.f32 "
        "{%0,%1,%2,%3}, {%4,%5,%6,%7}, {%8,%9}, {%0,%1,%2,%3};"
        : "+f"(d[0]), "+f"(d[1]), "+f"(d[2]), "+f"(d[3])
        : "r"(a[0]), "r"(a[1]), "r"(a[2]), "r"(a[3]), "r"(b[0]), "r"(b[1]));
}

__global__ __launch_bounds__(256)
void scores_mma_kernel()
{
    __shared__ __align__(16) char sbuf[128 * SMMA_STRIDE * 2 * 2];  // 36864 B
    __nv_bfloat16* As = (__nv_bfloat16*)sbuf;                       // [128][72]
    __nv_bfloat16* Bs = (__nv_bfloat16*)(sbuf + 128 * SMMA_STRIDE * 2);
    __nv_bfloat16* St = (__nv_bfloat16*)sbuf;                       // staging [128][136]

    const int tid  = threadIdx.x;
    const int wid  = tid >> 5;
    const int lane = tid & 31;
    const int wm   = wid & 3;        // warp M position (32 rows)
    const int wn   = wid >> 2;       // warp N position (64 cols)
    const int kt = blockIdx.x, qt = blockIdx.y, bh = blockIdx.z;

    const uint32_t as_b = (uint32_t)__cvta_generic_to_shared(As);
    const uint32_t bs_b = (uint32_t)__cvta_generic_to_shared(Bs);

    float acc[2][8][4];
    #pragma unroll
    for (int mf = 0; mf < 2; ++mf)
        #pragma unroll
        for (int nf = 0; nf < 8; ++nf)
            #pragma unroll
            for (int e = 0; e < 4; ++e) acc[mf][nf][e] = 0.f;

    // tile copy: thread t -> row t>>1, 4 uint4 (32 bf16) at half (t&1)
    const int crow = tid >> 1;
    const int ccol = (tid & 1) * 32;
    {
        const uint4* srcA = (const uint4*)(g_Qb + ((size_t)bh * L + qt * 128 + crow) * DK + ccol);
        const uint4* srcB = (const uint4*)(g_Kb + ((size_t)bh * L + kt * 128 + crow) * DK + ccol);
        uint4* dA = (uint4*)(As + crow * SMMA_STRIDE + ccol);
        uint4* dB = (uint4*)(Bs + crow * SMMA_STRIDE + ccol);
        #pragma unroll
        for (int i = 0; i < 4; ++i) { dA[i] = srcA[i]; dB[i] = srcB[i]; }
    }
    __syncthreads();

    #pragma unroll
    for (int kk = 0; kk < 64; kk += 16) {
        uint32_t af[2][4], bf[8][2];
        #pragma unroll
        for (int mf = 0; mf < 2; ++mf) {
            const int r = wm * 32 + mf * 16 + (lane & 15);
            const int c = kk + (lane >> 4) * 8;
            ldsm_x4(af[mf][0], af[mf][1], af[mf][2], af[mf][3],
                    as_b + (uint32_t)(r * SMMA_STRIDE + c) * 2u);
        }
        #pragma unroll
        for (int p = 0; p < 4; ++p) {
            const int n = wn * 64 + (2 * p + (lane >> 4)) * 8 + (lane & 7);
            const int c = kk + ((lane >> 3) & 1) * 8;
            ldsm_x4(bf[2 * p][0], bf[2 * p][1], bf[2 * p + 1][0], bf[2 * p + 1][1],
                    bs_b + (uint32_t)(n * SMMA_STRIDE + c) * 2u);
        }
        #pragma unroll
        for (int mf = 0; mf < 2; ++mf)
            #pragma unroll
            for (int nf = 0; nf < 8; ++nf)
                mma_bf16(acc[mf][nf], af[mf], bf[nf]);
    }

    // ---- stage: scale 1/8, bf16x2, mma-layout writes into smem ----
    __syncthreads();   // done reading As/Bs; reuse as staging
    #pragma unroll
    for (int mf = 0; mf < 2; ++mf)
        #pragma unroll
        for (int nf = 0; nf < 8; ++nf) {
            const int lr = wm * 32 + mf * 16 + (lane >> 2);
            const int lcx = wn * 64 + nf * 8 + (lane & 3) * 2;
            __nv_bfloat162 p0 = __float22bfloat162_rn(
                make_float2(acc[mf][nf][0] * 0.125f, acc[mf][nf][1] * 0.125f));
            __nv_bfloat162 p1 = __float22bfloat162_rn(
                make_float2(acc[mf][nf][2] * 0.125f, acc[mf][nf][3] * 0.125f));
            *(__nv_bfloat162*)&St[lr * STG_STRIDE + lcx] = p0;
            *(__nv_bfloat162*)&St[(lr + 8) * STG_STRIDE + lcx] = p1;
        }
    __syncthreads();

    // ---- coalesced store: thread -> row tid>>1, 128B half (tid&1) ----
    {
        const int rr = tid >> 1;
        const int hh = (tid & 1) * 64;
        __nv_bfloat16* grow = g_Sb + ((size_t)bh * L + qt * 128 + rr) * L + kt * 128 + hh;
        const __nv_bfloat16* srow2 = St + rr * STG_STRIDE + hh;
        #pragma unroll
        for (int k = 0; k < 8; ++k) {
            uint4 v = *(const uint4*)(srow2 + k * 8);
            __stcs((uint4*)(grow + k * 8), v);
        }
    }
}

// =====================================================================
// Kernel 3: approx top-38 on packed 16-bit bf16 keys (SIMD search) +
// margin 0.08 -> exact fp32 candidate refinement -> exact top-38 +
// softmax + sparse AV.  Warp per (bh,q) row.
// Packed reg t (t=0..31): c=t>>2, j=t&3; halves (lo,hi) hold score
// indices c*256 + lane*8 + 2j and +1.
// =====================================================================
__device__ __forceinline__ unsigned f2key(float f)
{
    unsigned u = __float_as_uint(f);
    return u ^ (((unsigned)((int)u >> 31)) | 0x80000000u);
}
__device__ __forceinline__ float key2f(unsigned k)
{
    unsigned u = (k & 0x80000000u) ? (k ^ 0x80000000u) : ~k;
    return __uint_as_float(u);
}
// two bf16 -> two monotone 16-bit keys, SIMD
__device__ __forceinline__ unsigned key16x2(unsigned v)
{
    const unsigned t = (v >> 15) & 0x00010001u;
    return v ^ (t * 0x7FFFu + 0x80008000u);
}
__device__ __forceinline__ unsigned key16_from_bf16(unsigned short b)
{
    return (b & 0x8000u) ? (unsigned)(~b & 0xFFFFu) : (unsigned)(b ^ 0x8000u);
}
__device__ __forceinline__ float key16_to_float(unsigned k)
{
    const unsigned bits16 = (k & 0x8000u) ? (k ^ 0x8000u) : (~k & 0xFFFFu);
    return __uint_as_float(bits16 << 16);
}

__global__ __launch_bounds__(256)
void topk_av_kernel()
{
    __shared__ float          s_w[8][NC];
    __shared__ unsigned short s_i[8][NC];
    __shared__ float          s_q[8][64];

    const int w    = threadIdx.x >> 5;
    const int lane = threadIdx.x & 31;
    const int row  = blockIdx.x * 8 + w;
    const int bh   = row >> 11;
    const int q    = row & 2047;

    const __nv_bfloat16* srow = g_Sb + (size_t)row * L;

    unsigned u2[32];
    #pragma unroll
    for (int c = 0; c < 8; ++c) {
        const uint4 f = __ldcs((const uint4*)(srow + c * 256 + lane * 8));
        u2[c * 4 + 0] = key16x2(f.x);
        u2[c * 4 + 1] = key16x2(f.y);
        u2[c * 4 + 2] = key16x2(f.z);
        u2[c * 4 + 3] = key16x2(f.w);
    }

    // ---- approx 38th-largest: 16-iteration bit search, SIMD counts ----
    unsigned T16 = 0;
    bool found = false;
    for (int b = 15; b >= 0 && !found; --b) {
        const unsigned cand  = T16 | (1u << b);
        const unsigned cand2 = cand * 0x00010001u;
        unsigned a2 = 0;
        #pragma unroll
        for (int t = 0; t < 32; ++t) a2 += __vsetgeu2(u2[t], cand2);
        int cnt = (int)((a2 & 0xFFFFu) + (a2 >> 16));
        cnt = __reduce_add_sync(FULLMASK, cnt);
        if (cnt >= U) T16 = cand;
        if (cnt == U) found = true;
    }
    {   // tighten to min selected key (handles ties / early exit)
        unsigned mn = 0xFFFFu;
        #pragma unroll
        for (int t = 0; t < 32; ++t) {
            const unsigned lo = u2[t] & 0xFFFFu, hi = u2[t] >> 16;
            if (lo >= T16) mn = min(mn, lo);
            if (hi >= T16) mn = min(mn, hi);
        }
        T16 = __reduce_min_sync(FULLMASK, mn);
    }

    // ---- candidates: approx >= T - margin (floor-rounded to bf16) ----
    const float tf = key16_to_float(T16) - 0.08f;
    const __nv_bfloat16 tb = __float2bfloat16_rd(tf);
    const unsigned Tc16 = key16_from_bf16(*(const unsigned short*)&tb);

    int base = 0;
    #pragma unroll
    for (int t = 0; t < 32; ++t) {
        const int idx0 = (t >> 2) * 256 + lane * 8 + 2 * (t & 3);
        {
            const bool sel = (u2[t] & 0xFFFFu) >= Tc16;
            const unsigned bal = __ballot_sync(FULLMASK, sel);
            if (sel) {
                const int p = base + __popc(bal & ((1u << lane) - 1u));
                if (p < NC) s_i[w][p] = (unsigned short)idx0;
            }
            base += __popc(bal);
        }
        {
            const bool sel = (u2[t] >> 16) >= Tc16;
            const unsigned bal = __ballot_sync(FULLMASK, sel);
            if (sel) {
                const int p = base + __popc(bal & ((1u << lane) - 1u));
                if (p < NC) s_i[w][p] = (unsigned short)(idx0 + 1);
            }
            base += __popc(bal);
        }
    }
    const int nsel = min(base, NC);

    // ---- exact fp32 recompute of candidate scores ----
    {
        const float2 q2 = *(const float2*)(g_Q + ((size_t)bh * L + q) * DK + 2 * lane);
        s_q[w][2 * lane]     = q2.x;
        s_q[w][2 * lane + 1] = q2.y;
    }
    __syncwarp();
    const float* Kbh = g_K + (size_t)bh * L * DK;
    #pragma unroll
    for (int cc = 0; cc < 3; ++cc) {
        const int j = lane + 32 * cc;
        float sc = -1e30f;
        if (j < nsel) {
            const float4* kr = (const float4*)(Kbh + (size_t)s_i[w][j] * DK);
            const float4* qr = (const float4*)s_q[w];
            float a = 0.f;
            #pragma unroll
            for (int i = 0; i < 16; ++i) {
                const float4 kv = kr[i], qv = qr[i];
                a += kv.x * qv.x + kv.y * qv.y + kv.z * qv.z + kv.w * qv.w;
            }
            sc = a * 0.125f;
        }
        s_w[w][j] = sc;
    }
    __syncwarp();

    // ---- exact top-38 among candidates ----
    float ev[3]; unsigned short iv[3]; unsigned kv3[3];
    #pragma unroll
    for (int cc = 0; cc < 3; ++cc) {
        ev[cc] = s_w[w][lane + 32 * cc];
        iv[cc] = s_i[w][lane + 32 * cc];
        kv3[cc] = f2key(ev[cc]);
    }
    const unsigned mk = __reduce_max_sync(FULLMASK, max(kv3[0], max(kv3[1], kv3[2])));
    const float m = key2f(mk);

    unsigned Te = 0;
    found = false;
    for (int b = 31; b >= 0 && !found; --b) {
        const unsigned cand = Te | (1u << b);
        const int cnt = __reduce_add_sync(FULLMASK,
            (int)(kv3[0] >= cand) + (int)(kv3[1] >= cand) + (int)(kv3[2] >= cand));
        if (cnt >= U) Te = cand;
        if (cnt == U) found = true;
    }
    {
        unsigned mn = 0xFFFFFFFFu;
        #pragma unroll
        for (int cc = 0; cc < 3; ++cc)
            if (kv3[cc] >= Te) mn = min(mn, kv3[cc]);
        Te = __reduce_min_sync(FULLMASK, mn);
    }

    // ---- exact softmax weights + compact selected ----
    float wv[3]; float Z = 0.f;
    #pragma unroll
    for (int cc = 0; cc < 3; ++cc) {
        wv[cc] = (kv3[cc] >= Te) ? __expf(ev[cc] - m) : 0.f;
        Z += wv[cc];
    }
    #pragma unroll
    for (int off = 16; off; off >>= 1)
        Z += __shfl_xor_sync(FULLMASK, Z, off);
    const float invZ = 1.f / Z;

    int nsel2 = 0;
    __syncwarp();
    #pragma unroll
    for (int cc = 0; cc < 3; ++cc) {
        const bool sel = (kv3[cc] >= Te);
        const unsigned bal = __ballot_sync(FULLMASK, sel);
        if (sel) {
            const int p = nsel2 + __popc(bal & ((1u << lane) - 1u));
            s_w[w][p] = wv[cc]; s_i[w][p] = iv[cc];
        }
        nsel2 += __popc(bal);
    }
    __syncwarp();

    // ---- batched sparse AV over selected list ----
    const float* Vh = g_V + (size_t)bh * L * DK;
    float o0 = 0.f, o1 = 0.f;
    int j = 0;
    for (; j + 4 <= nsel2; j += 4) {
        const float a0 = s_w[w][j],     a1 = s_w[w][j + 1];
        const float a2 = s_w[w][j + 2], a3 = s_w[w][j + 3];
        const float* v0 = Vh + (size_t)s_i[w][j]     * DK;
        const float* v1 = Vh + (size_t)s_i[w][j + 1] * DK;
        const float* v2 = Vh + (size_t)s_i[w][j + 2] * DK;
        const float* v3 = Vh + (size_t)s_i[w][j + 3] * DK;
        const float x0 = v0[lane], y0 = v0[lane + 32];
        const float x1 = v1[lane], y1 = v1[lane + 32];
        const float x2 = v2[lane], y2 = v2[lane + 32];
        const float x3 = v3[lane], y3 = v3[lane + 32];
        o0 += a0 * x0 + a1 * x1 + a2 * x2 + a3 * x3;
        o1 += a0 * y0 + a1 * y1 + a2 * y2 + a3 * y3;
    }
    for (; j < nsel2; ++j) {
        const float wj = s_w[w][j];
        const float* vr = Vh + (size_t)s_i[w][j] * DK;
        o0 += wj * vr[lane];
        o1 += wj * vr[lane + 32];
    }

    const int b = bh >> 3, h = bh & 7;
    float* ao = g_AO + (size_t)(b * L + q) * DM + h * DK;
    ao[lane]      = o0 * invZ;
    ao[lane + 32] = o1 * invZ;
}

// =====================================================================
// Kernel 4: out = AO @ Wo^T + bo.  grid (DM/128, B*L/64)
// =====================================================================
__global__ __launch_bounds__(256)
void outproj_kernel(const float* __restrict__ Wo, const float* __restrict__ bo,
                    float* __restrict__ out)
{
    const float* A  = g_AO + (size_t)blockIdx.y * 64 * DM;
    const float* Bm = Wo   + (size_t)blockIdx.x * 128 * DM;

    float acc[4][8];
    gemm_core_64x128(A, Bm, DM, DM, DM, acc);

    const int tx = threadIdx.x & 15, ty = threadIdx.x >> 4;
    #pragma unroll
    for (int i = 0; i < 4; ++i) {
        const int r = blockIdx.y * 64 + ty * 4 + i;
        #pragma unroll
        for (int jh = 0; jh < 2; ++jh) {
            const int cc = blockIdx.x * 128 + (jh ? 64 + tx * 4 : tx * 4);
            float4 v = make_float4(acc[i][jh * 4 + 0] + bo[cc + 0],
                                   acc[i][jh * 4 + 1] + bo[cc + 1],
                                   acc[i][jh * 4 + 2] + bo[cc + 2],
                                   acc[i][jh * 4 + 3] + bo[cc + 3]);
            *(float4*)&out[(size_t)r * DM + cc] = v;
        }
    }
}

// =====================================================================
extern "C" void kernel_launch(void* const* d_in, const int* in_sizes, int n_in,
                              void* d_out, int out_size)
{
    const float* x  = (const float*)d_in[0];
    const float* Wq = (const float*)d_in[1];
    const float* bq = (const float*)d_in[2];
    const float* Wk = (const float*)d_in[3];
    const float* bk = (const float*)d_in[4];
    const float* Wv = (const float*)d_in[5];
    const float* bv = (const float*)d_in[6];
    const float* Wo = (const float*)d_in[7];
    const float* bo = (const float*)d_in[8];
    float* out = (float*)d_out;

    dim3 blk(256);
    proj_kernel<<<dim3(DM / 128, (Bb * L) / 64, 3), blk>>>(x, Wq, bq, Wk, bk, Wv, bv);
    scores_mma_kernel<<<dim3(L / 128, L / 128, BH), blk>>>();
    topk_av_kernel<<<(BH * L) / 8, blk>>>();
    outproj_kernel<<<dim3(DM / 128, (Bb * L) / 64), blk>>>(Wo, bo, out);
}